// round 14
// baseline (speedup 1.0000x reference)
#include <cuda_runtime.h>
#include <cuda_bf16.h>

// ---------------------------------------------------------------------------
// Problem constants
// ---------------------------------------------------------------------------
#define BATCH 8
#define CHANNELS 1024
#define HW 2304           // 48*48
#define POOL_P 576        // 24*24
#define POS_TOTAL (BATCH*POOL_P*POOL_P)   // 2,654,208
#define EPS_L2 1e-6f
#define EPS_MM 1e-5f

typedef unsigned long long u64;

// ---------------------------------------------------------------------------
// Scratch (device globals; no allocation allowed)
// ---------------------------------------------------------------------------
__device__ float g_A[BATCH * HW * CHANNELS];
__device__ float g_B[BATCH * HW * CHANNELS];
__device__ float g_invnA[BATCH * HW];
__device__ float g_invnB[BATCH * HW];
__device__ float g_cpool[POS_TOTAL];
__device__ float g_x1[BATCH * 10 * POOL_P * POOL_P];
__device__ float g_x2[BATCH * 10 * POOL_P * POOL_P];
__device__ float g_amax[BATCH * POOL_P];      // max -> reciprocal (in place)
__device__ float g_bmax[BATCH * POOL_P];

// ---------------------------------------------------------------------------
// Helpers
// ---------------------------------------------------------------------------
__device__ __forceinline__ unsigned smem_u32(const void* p) {
    return (unsigned)__cvta_generic_to_shared(p);
}
__device__ __forceinline__ u64 pack2(float a, float b) {
    u64 r; asm("mov.b64 %0, {%1, %2};" : "=l"(r) : "f"(a), "f"(b)); return r;
}
__device__ __forceinline__ void fma2(u64& d, u64 a, u64 b) {
    asm("fma.rn.f32x2 %0, %1, %2, %0;" : "+l"(d) : "l"(a), "l"(b));
}
__device__ __forceinline__ float2 unpack2(u64 v) {
    float2 r; asm("mov.b64 {%0, %1}, %2;" : "=f"(r.x), "=f"(r.y) : "l"(v)); return r;
}
__device__ __forceinline__ float tf32r(float v) {
    unsigned t; asm("cvt.rna.tf32.f32 %0, %1;" : "=r"(t) : "f"(v));
    return __uint_as_float(t);
}

// ---------------------------------------------------------------------------
// 1) inverse L2 norm per (b, hw)
// ---------------------------------------------------------------------------
__global__ void invnorm_kernel(const float* __restrict__ A, const float* __restrict__ B) {
    int t = blockIdx.x * blockDim.x + threadIdx.x;
    if (t >= 2 * BATCH * HW) return;
    const float* f = (t < BATCH * HW) ? A : B;
    float* o = (t < BATCH * HW) ? g_invnA : g_invnB;
    int idx = t % (BATCH * HW);
    int b = idx / HW, hw = idx % HW;
    const float* p = f + (size_t)b * CHANNELS * HW + hw;
    float s = 0.f;
#pragma unroll 16
    for (int c = 0; c < CHANNELS; ++c) {
        float v = p[(size_t)c * HW];
        s = fmaf(v, v, s);
    }
    o[idx] = rsqrtf(s + EPS_L2);
}

// ---------------------------------------------------------------------------
// 2) transpose + normalize + tf32-round into MMA-fragment layout (one launch)
// ---------------------------------------------------------------------------
__global__ __launch_bounds__(256) void transnorm_kernel(
    const float* __restrict__ fA, const float* __restrict__ fB,
    const float* __restrict__ invA, const float* __restrict__ invB,
    float* __restrict__ outA, float* __restrict__ outB) {
    __shared__ float sm[32][33];
    int zz = blockIdx.z;
    int mode = zz >> 3;
    int b = zz & 7;
    const float* f = mode ? fB : fA;
    const float* invn = mode ? invB : invA;
    float* out = mode ? outB : outA;

    int pb = blockIdx.x;
    int c0 = blockIdx.y * 32;
    int g0 = pb * 8;
    int hbase = (g0 / 24) * 2;
    int wbase = (g0 % 24) * 2;
    int tid = threadIdx.x;

    for (int idx = tid; idx < 1024; idx += 256) {
        int ci = idx >> 5, pos = idx & 31;
        int hh = pos >> 4, ww = pos & 15;
        int hw = (hbase + hh) * 48 + wbase + ww;
        float v = f[((size_t)b * CHANNELS + c0 + ci) * HW + hw] * invn[b * HW + hw];
        int p_in = ((ww >> 1) << 2) | (hh << 1) | (ww & 1);
        sm[p_in][ci] = tf32r(v);
    }
    __syncthreads();

    int p0 = pb * 32;
    if (mode == 0) {
        int mt = tid >> 7, kt = (tid >> 5) & 3, lane = tid & 31;
        int rowin = lane >> 2, colin = lane & 3;
        float4 v;
        v.x = sm[mt * 16 + rowin][kt * 8 + colin];
        v.y = sm[mt * 16 + rowin + 8][kt * 8 + colin];
        v.z = sm[mt * 16 + rowin][kt * 8 + colin + 4];
        v.w = sm[mt * 16 + rowin + 8][kt * 8 + colin + 4];
        int rowblk = p0 >> 7;
        int mtile_g = ((p0 >> 4) & 7) + mt;
        int ktile_g = (c0 >> 3) + kt;
        size_t off = ((((size_t)b * 18 + rowblk) * 128 + ktile_g) * 8 + mtile_g) * 128
                     + lane * 4;
        *(float4*)(out + off) = v;
    } else {
        int colblk = p0 >> 7;
#pragma unroll
        for (int i = 0; i < 2; ++i) {
            int id = tid + i * 256;
            int nt = id >> 7, kt = (id >> 5) & 3, lane = id & 31;
            int rowin = lane >> 2, colin = lane & 3;
            float2 v;
            v.x = sm[nt * 8 + rowin][kt * 8 + colin];
            v.y = sm[nt * 8 + rowin][kt * 8 + colin + 4];
            int ntile_g = ((p0 >> 3) & 15) + nt;
            int ktile_g = (c0 >> 3) + kt;
            size_t off = ((((size_t)b * 18 + colblk) * 128 + ktile_g) * 16 + ntile_g) * 64
                         + lane * 2;
            *(float2*)(out + off) = v;
        }
    }
}

// ---------------------------------------------------------------------------
// 3) batched TF32 GEMM + fused 4x4 max-pool + relu/L2 + row/col max reduce.
//    amax/bmax must be zeroed beforehand (atomicMax-as-int on >=0 floats).
// ---------------------------------------------------------------------------
#define STAGE_FLOATS 4096   // 4 ktiles * 1024 floats

__global__ __launch_bounds__(128) void gemm_pool_kernel(
    const float* __restrict__ A, const float* __restrict__ B,
    float* __restrict__ out, float* __restrict__ amax, float* __restrict__ bmax) {
    extern __shared__ char smem_raw[];
    float* As = (float*)smem_raw;            // [3][4096]
    float* Bs = As + 3 * STAGE_FLOATS;       // [3][4096]
    float* Cs = (float*)smem_raw;            // reused: [128][132]
    __shared__ int rm_s[32], cm_s[32];

    int b = blockIdx.z;
    const float* Ag = A + (size_t)b * HW * CHANNELS + (size_t)blockIdx.y * 128 * 1024;
    const float* Bg = B + (size_t)b * HW * CHANNELS + (size_t)blockIdx.x * 128 * 1024;

    int tid = threadIdx.x, lane = tid & 31, wid = tid >> 5;
    int wm = wid >> 1, wn = wid & 1;   // 2x2 warp grid, warp tile 64x64

    float acc[4][8][4];
#pragma unroll
    for (int i = 0; i < 4; ++i)
#pragma unroll
        for (int j = 0; j < 8; ++j)
#pragma unroll
            for (int k = 0; k < 4; ++k) acc[i][j][k] = 0.f;

    auto load_stage = [&](int s, int kt) {
        const float* ga = Ag + (size_t)kt * STAGE_FLOATS;
        const float* gb = Bg + (size_t)kt * STAGE_FLOATS;
#pragma unroll
        for (int i = 0; i < 8; ++i) {
            int idx = tid + i * 128;
            unsigned sa = smem_u32(As + s * STAGE_FLOATS + idx * 4);
            asm volatile("cp.async.cg.shared.global [%0], [%1], 16;\n" :: "r"(sa), "l"(ga + idx * 4));
            unsigned sb = smem_u32(Bs + s * STAGE_FLOATS + idx * 4);
            asm volatile("cp.async.cg.shared.global [%0], [%1], 16;\n" :: "r"(sb), "l"(gb + idx * 4));
        }
        asm volatile("cp.async.commit_group;\n");
    };

    const int KT = CHANNELS / 32;
    load_stage(0, 0);
    load_stage(1, 1);
    for (int kt = 0; kt < KT; ++kt) {
        if (kt + 2 < KT) {
            asm volatile("cp.async.wait_group 1;\n");
        } else {
            asm volatile("cp.async.wait_group 0;\n");
        }
        __syncthreads();
        if (kt + 2 < KT) load_stage((kt + 2) % 3, kt + 2);
        int cur = kt % 3;
        const float* Ab = As + cur * STAGE_FLOATS;
        const float* Bb = Bs + cur * STAGE_FLOATS;
#pragma unroll
        for (int kk = 0; kk < 4; ++kk) {
            uint2 bf[8];
#pragma unroll
            for (int ni = 0; ni < 8; ++ni)
                bf[ni] = *(const uint2*)(Bb + ((kk * 16 + wn * 8 + ni) * 32 + lane) * 2);
#pragma unroll
            for (int mi = 0; mi < 4; ++mi) {
                uint4 af = *(const uint4*)(Ab + ((kk * 8 + wm * 4 + mi) * 32 + lane) * 4);
#pragma unroll
                for (int ni = 0; ni < 8; ++ni) {
                    asm volatile(
                        "mma.sync.aligned.m16n8k8.row.col.f32.tf32.tf32.f32 "
                        "{%0,%1,%2,%3}, {%4,%5,%6,%7}, {%8,%9}, {%0,%1,%2,%3};\n"
                        : "+f"(acc[mi][ni][0]), "+f"(acc[mi][ni][1]),
                          "+f"(acc[mi][ni][2]), "+f"(acc[mi][ni][3])
                        : "r"(af.x), "r"(af.y), "r"(af.z), "r"(af.w),
                          "r"(bf[ni].x), "r"(bf[ni].y));
                }
            }
        }
    }
    __syncthreads();

#pragma unroll
    for (int mi = 0; mi < 4; ++mi) {
#pragma unroll
        for (int ni = 0; ni < 8; ++ni) {
            int r0 = wm * 64 + mi * 16 + (lane >> 2);
            int c0 = wn * 64 + ni * 8 + (lane & 3) * 2;
            Cs[r0 * 132 + c0]           = acc[mi][ni][0];
            Cs[r0 * 132 + c0 + 1]       = acc[mi][ni][1];
            Cs[(r0 + 8) * 132 + c0]     = acc[mi][ni][2];
            Cs[(r0 + 8) * 132 + c0 + 1] = acc[mi][ni][3];
        }
    }
    if (tid < 32) { rm_s[tid] = 0; cm_s[tid] = 0; }
    __syncthreads();

#pragma unroll
    for (int o = 0; o < 8; ++o) {
        int idx = tid * 8 + o;
        int pp = idx >> 5, qq = idx & 31;
        float m = -1e30f;
#pragma unroll
        for (int i = 0; i < 4; ++i)
#pragma unroll
            for (int j = 0; j < 4; ++j)
                m = fmaxf(m, Cs[(pp * 4 + i) * 132 + qq * 4 + j]);
        m = fmaxf(m, 0.f);
        float v = m * rsqrtf(m * m + EPS_L2);
        out[((size_t)b * POOL_P + blockIdx.y * 32 + pp) * POOL_P + blockIdx.x * 32 + qq] = v;
        atomicMax(&rm_s[pp], __float_as_int(v));
        atomicMax(&cm_s[qq], __float_as_int(v));
    }
    __syncthreads();
    if (tid < 32) {
        atomicMax((int*)&amax[b * POOL_P + blockIdx.y * 32 + tid], rm_s[tid]);
        atomicMax((int*)&bmax[b * POOL_P + blockIdx.x * 32 + tid], cm_s[tid]);
    }
}

// ---------------------------------------------------------------------------
// 4) fused single-pass row+col maxes (pass #2 only; bmax pre-zeroed)
// ---------------------------------------------------------------------------
__global__ __launch_bounds__(256) void maxfused_kernel(
    const float* __restrict__ X, float* __restrict__ amax, float* __restrict__ bmax) {
    __shared__ int colm_s[POOL_P];
    int b = blockIdx.y;
    int r0 = blockIdx.x * 64;
    int tid = threadIdx.x, lane = tid & 31, wid = tid >> 5;

    for (int i = tid; i < POOL_P; i += 256) colm_s[i] = 0;
    __syncthreads();

    float colm[18];
#pragma unroll
    for (int i = 0; i < 18; ++i) colm[i] = 0.f;

    const float* base = X + (size_t)b * POOL_P * POOL_P;
#pragma unroll
    for (int rr = 0; rr < 8; ++rr) {
        int row = r0 + wid * 8 + rr;
        const float* p = base + (size_t)row * POOL_P;
        float rm = 0.f;
#pragma unroll
        for (int i = 0; i < 18; ++i) {
            float v = p[lane + i * 32];
            rm = fmaxf(rm, v);
            colm[i] = fmaxf(colm[i], v);
        }
#pragma unroll
        for (int s = 16; s; s >>= 1) rm = fmaxf(rm, __shfl_down_sync(0xffffffffu, rm, s));
        if (lane == 0) amax[b * POOL_P + row] = rm;
    }
#pragma unroll
    for (int i = 0; i < 18; ++i)
        atomicMax(&colm_s[lane + i * 32], __float_as_int(colm[i]));
    __syncthreads();
    for (int i = tid; i < POOL_P; i += 256)
        atomicMax((int*)&bmax[b * POOL_P + i], colm_s[i]);
}

// convert max -> 1/(max+eps)
__global__ void recip_kernel(float* __restrict__ amax, float* __restrict__ bmax) {
    int i = blockIdx.x * blockDim.x + threadIdx.x;
    if (i < BATCH * POOL_P) {
        amax[i] = 1.0f / (amax[i] + EPS_MM);
        bmax[i] = 1.0f / (bmax[i] + EPS_MM);
    }
}

// ---------------------------------------------------------------------------
// 5) mutual matching, float4 (pass #2 only)
// ---------------------------------------------------------------------------
__global__ __launch_bounds__(256) void mm_kernel(
    const float* __restrict__ X, const float* __restrict__ am,
    const float* __restrict__ bm, float* __restrict__ O) {
    int i4 = blockIdx.x * blockDim.x + threadIdx.x;
    if (i4 >= POS_TOTAL / 4) return;
    int i = i4 * 4;
    int q = i % POOL_P;
    int pr = (i / POOL_P) % POOL_P;
    int b = i / (POOL_P * POOL_P);
    float a = am[b * POOL_P + pr];
    const float* bp = bm + b * POOL_P + q;
    float4 c = *(const float4*)(X + i);
    float4 o;
    o.x = c.x * (c.x * a) * (c.x * bp[0]);
    o.y = c.y * (c.y * a) * (c.y * bp[1]);
    o.z = c.z * (c.z * a) * (c.z * bp[2]);
    o.w = c.w * (c.w * a) * (c.w * bp[3]);
    *(float4*)(O + i) = o;
}

// ---------------------------------------------------------------------------
// 6) Conv4d FFMA2 v4 (conv2): 2x2 tile/thread, CTA-uniform j1 skip.
// ---------------------------------------------------------------------------
#define RSTR 36              // plane row stride (floats)
#define CSTR (26 * RSTR)     // 936 floats per channel

template <int CIN, int COUT>
__global__ __launch_bounds__(288) void conv4d_v4_kernel(
    const float* __restrict__ in, const float* __restrict__ w,
    const float* __restrict__ bias, float* __restrict__ out) {
    constexpr int CP2 = (COUT + 1) & ~1;
    constexpr int COP = CP2 / 2;
    constexpr int WPAD = (CIN * 81 * CP2 + 3) & ~3;
    constexpr int PLN = CIN * CSTR;
    extern __shared__ float sm[];
    float* wsm = sm;
    float* pl = sm + WPAD;

    int tid = threadIdx.x;
    int b = blockIdx.z, x1 = blockIdx.y, bx = blockIdx.x;
    int half = tid / 144, u = tid % 144;
    int x3 = 2 * (u / 12), x4 = 2 * (u % 12);
    int x2 = bx * 2 + half;

    for (int i = tid; i < CIN * 81 * CP2; i += 288) {
        int co = i % CP2;
        int rest = i / CP2;
        int ci = rest / 81, tap = rest % 81;
        wsm[i] = (co < COUT) ? w[(co * CIN + ci) * 81 + tap] : 0.f;
    }
    for (int i = tid; i < 2 * CIN * 26; i += 288) {
        int h = i / (CIN * 26), r = i % (CIN * 26);
        int ci = r / 26, rr = r % 26;
        float* rowp = pl + h * PLN + ci * CSTR + rr * RSTR;
        if (rr == 0 || rr == 25) {
            for (int c = 3; c <= 28; ++c) rowp[c] = 0.f;
        } else {
            rowp[3] = 0.f; rowp[28] = 0.f;
        }
    }

    u64 acc[COP][4];
#pragma unroll
    for (int cp = 0; cp < COP; ++cp)
#pragma unroll
        for (int o = 0; o < 4; ++o) acc[cp][o] = 0ull;

    for (int j1 = 0; j1 < 3; ++j1) {
        int y1 = x1 + j1 - 1;
        if ((unsigned)y1 >= 24u) continue;
        for (int j2 = 0; j2 < 3; ++j2) {
            __syncthreads();
            for (int t = tid; t < 2 * CIN * 24; t += 288) {
                int h = t / (CIN * 24), r = t % (CIN * 24);
                int ci = r / 24, rr = 1 + r % 24;
                int y2 = bx * 2 + h + j2 - 1;
                float* dst = pl + h * PLN + ci * CSTR + rr * RSTR + 4;
                if ((unsigned)y2 < 24u) {
                    const float* src = in + ((((size_t)b * CIN + ci) * 24 + y1) * 24 + y2) * POOL_P
                                          + (rr - 1) * 24;
#pragma unroll
                    for (int c = 0; c < 6; ++c)
                        *(float4*)(dst + c * 4) = *(const float4*)(src + c * 4);
                } else {
                    float4 z = make_float4(0.f, 0.f, 0.f, 0.f);
#pragma unroll
                    for (int c = 0; c < 6; ++c) *(float4*)(dst + c * 4) = z;
                }
            }
            __syncthreads();

            const float* base = pl + half * PLN;
            for (int ci = 0; ci < CIN; ++ci) {
#pragma unroll
                for (int j3 = 0; j3 < 3; ++j3) {
                    const float* r0 = base + ci * CSTR + (x3 + j3) * RSTR + 3 + x4;
                    const float* r1 = r0 + RSTR;
                    u64 vd0[4], vd1[4];
#pragma unroll
                    for (int t = 0; t < 4; ++t) {
                        float a = r0[t]; vd0[t] = pack2(a, a);
                        float c2 = r1[t]; vd1[t] = pack2(c2, c2);
                    }
                    const float* wb = wsm + (ci * 81 + j1 * 27 + j2 * 9 + j3 * 3) * CP2;
#pragma unroll
                    for (int j4 = 0; j4 < 3; ++j4) {
#pragma unroll
                        for (int cp = 0; cp < COP; ++cp) {
                            u64 wp = *reinterpret_cast<const u64*>(wb + j4 * CP2 + cp * 2);
                            fma2(acc[cp][0], wp, vd0[j4]);
                            fma2(acc[cp][1], wp, vd0[j4 + 1]);
                            fma2(acc[cp][2], wp, vd1[j4]);
                            fma2(acc[cp][3], wp, vd1[j4 + 1]);
                        }
                    }
                }
            }
        }
    }

    int pos0 = x3 * 24 + x4;
#pragma unroll
    for (int cp = 0; cp < COP; ++cp) {
        int co0 = 2 * cp, co1 = co0 + 1;
        float2 q0 = unpack2(acc[cp][0]);
        float2 q1 = unpack2(acc[cp][1]);
        float2 q2 = unpack2(acc[cp][2]);
        float2 q3 = unpack2(acc[cp][3]);
        float b0 = bias[co0];
        size_t base0 = ((((size_t)b * COUT + co0) * 24 + x1) * 24 + x2) * POOL_P + pos0;
        *(float2*)(out + base0)      = make_float2(fmaxf(q0.x + b0, 0.f), fmaxf(q1.x + b0, 0.f));
        *(float2*)(out + base0 + 24) = make_float2(fmaxf(q2.x + b0, 0.f), fmaxf(q3.x + b0, 0.f));
        if (co1 < COUT) {
            float b1 = bias[co1];
            size_t base1 = ((((size_t)b * COUT + co1) * 24 + x1) * 24 + x2) * POOL_P + pos0;
            *(float2*)(out + base1)      = make_float2(fmaxf(q0.y + b1, 0.f), fmaxf(q1.y + b1, 0.f));
            *(float2*)(out + base1 + 24) = make_float2(fmaxf(q2.y + b1, 0.f), fmaxf(q3.y + b1, 0.f));
        }
    }
}

// ---------------------------------------------------------------------------
// 6a) Conv1 (CIN=1): preload ALL 12 distinct haloed planes once, with
//     mutual-matching #1 applied at load (each element loaded exactly once).
// ---------------------------------------------------------------------------
template <int COUT>
__global__ __launch_bounds__(288) void conv4d_cin1_kernel(
    const float* __restrict__ in, const float* __restrict__ w,
    const float* __restrict__ bias, float* __restrict__ out,
    const float* __restrict__ ainv, const float* __restrict__ binv) {
    constexpr int CP2 = (COUT + 1) & ~1;
    constexpr int COP = CP2 / 2;
    constexpr int WPAD = (81 * CP2 + 3) & ~3;
    extern __shared__ float sm[];
    float* wsm = sm;                    // [81][CP2]
    float* pl = sm + WPAD;              // [12][CSTR]

    int tid = threadIdx.x;
    int b = blockIdx.z, x1 = blockIdx.y, bx = blockIdx.x;
    int half = tid / 144, u = tid % 144;
    int x3 = 2 * (u / 12), x4 = 2 * (u % 12);
    int x2 = bx * 2 + half;

    for (int i = tid; i < 81 * CP2; i += 288) {
        int co = i % CP2, tap = i / CP2;
        wsm[i] = (co < COUT) ? w[co * 81 + tap] : 0.f;
    }
    for (int i = tid; i < 12 * 26; i += 288) {
        int p = i / 26, rr = i % 26;
        float* rowp = pl + p * CSTR + rr * RSTR;
        if (rr == 0 || rr == 25) {
            for (int c = 3; c <= 28; ++c) rowp[c] = 0.f;
        } else {
            rowp[3] = 0.f; rowp[28] = 0.f;
        }
    }
    {
        int p = tid / 24, rr = 1 + tid % 24;
        int y1 = x1 + (p >> 2) - 1;
        int y2 = bx * 2 + (p & 3) - 1;
        float* dst = pl + p * CSTR + rr * RSTR + 4;
        if ((unsigned)y1 < 24u && (unsigned)y2 < 24u) {
            const float* src = in + (((size_t)b * 24 + y1) * 24 + y2) * POOL_P + (rr - 1) * 24;
            float a = ainv[b * POOL_P + y1 * 24 + y2];
            const float* bp = binv + b * POOL_P + (rr - 1) * 24;
#pragma unroll
            for (int c = 0; c < 6; ++c) {
                float4 vv = *(const float4*)(src + c * 4);
                const float* bq = bp + c * 4;
                vv.x = vv.x * (vv.x * a) * (vv.x * bq[0]);
                vv.y = vv.y * (vv.y * a) * (vv.y * bq[1]);
                vv.z = vv.z * (vv.z * a) * (vv.z * bq[2]);
                vv.w = vv.w * (vv.w * a) * (vv.w * bq[3]);
                *(float4*)(dst + c * 4) = vv;
            }
        } else {
            float4 z = make_float4(0.f, 0.f, 0.f, 0.f);
#pragma unroll
            for (int c = 0; c < 6; ++c) *(float4*)(dst + c * 4) = z;
        }
    }
    __syncthreads();

    u64 acc[COP][4];
#pragma unroll
    for (int cp = 0; cp < COP; ++cp)
#pragma unroll
        for (int o = 0; o < 4; ++o) acc[cp][o] = 0ull;

#pragma unroll
    for (int g = 0; g < 9; ++g) {
        int j1 = g / 3, j2 = g % 3;
        if ((unsigned)(x1 + j1 - 1) >= 24u) continue;
        const float* base = pl + (j1 * 4 + j2 + half) * CSTR;
#pragma unroll
        for (int j3 = 0; j3 < 3; ++j3) {
            const float* r0 = base + (x3 + j3) * RSTR + 3 + x4;
            const float* r1 = r0 + RSTR;
            u64 vd0[4], vd1[4];
#pragma unroll
            for (int t = 0; t < 4; ++t) {
                float a = r0[t]; vd0[t] = pack2(a, a);
                float c2 = r1[t]; vd1[t] = pack2(c2, c2);
            }
            const float* wb = wsm + (j1 * 27 + j2 * 9 + j3 * 3) * CP2;
#pragma unroll
            for (int j4 = 0; j4 < 3; ++j4) {
#pragma unroll
                for (int cp = 0; cp < COP; ++cp) {
                    u64 wp = *reinterpret_cast<const u64*>(wb + j4 * CP2 + cp * 2);
                    fma2(acc[cp][0], wp, vd0[j4]);
                    fma2(acc[cp][1], wp, vd0[j4 + 1]);
                    fma2(acc[cp][2], wp, vd1[j4]);
                    fma2(acc[cp][3], wp, vd1[j4 + 1]);
                }
            }
        }
    }

    int pos0 = x3 * 24 + x4;
#pragma unroll
    for (int cp = 0; cp < COP; ++cp) {
        int co0 = 2 * cp, co1 = co0 + 1;
        float2 q0 = unpack2(acc[cp][0]);
        float2 q1 = unpack2(acc[cp][1]);
        float2 q2 = unpack2(acc[cp][2]);
        float2 q3 = unpack2(acc[cp][3]);
        float b0 = bias[co0];
        size_t base0 = ((((size_t)b * COUT + co0) * 24 + x1) * 24 + x2) * POOL_P + pos0;
        *(float2*)(out + base0)      = make_float2(fmaxf(q0.x + b0, 0.f), fmaxf(q1.x + b0, 0.f));
        *(float2*)(out + base0 + 24) = make_float2(fmaxf(q2.x + b0, 0.f), fmaxf(q3.x + b0, 0.f));
        if (co1 < COUT) {
            float b1 = bias[co1];
            size_t base1 = ((((size_t)b * COUT + co1) * 24 + x1) * 24 + x2) * POOL_P + pos0;
            *(float2*)(out + base1)      = make_float2(fmaxf(q0.y + b1, 0.f), fmaxf(q1.y + b1, 0.f));
            *(float2*)(out + base1 + 24) = make_float2(fmaxf(q2.y + b1, 0.f), fmaxf(q3.y + b1, 0.f));
        }
    }
}

// ---------------------------------------------------------------------------
// 6b) Conv3 (COUT=1): row-pair f32x2; CTA-uniform j1 skip.
// ---------------------------------------------------------------------------
template <int CIN>
__global__ __launch_bounds__(288) void conv4d_c1_kernel(
    const float* __restrict__ in, const float* __restrict__ w,
    const float* __restrict__ bias, float* __restrict__ out) {
    constexpr int WPAD = (2 * CIN * 81 + 3) & ~3;
    constexpr int PLN = CIN * CSTR;
    extern __shared__ float sm[];
    float* wsm = sm;
    float* pl = sm + WPAD;

    int tid = threadIdx.x;
    int b = blockIdx.z, x1 = blockIdx.y, bx = blockIdx.x;
    int half = tid / 144, u = tid % 144;
    int x3 = 2 * (u / 12), x4 = 2 * (u % 12);
    int x2 = bx * 2 + half;

    for (int i = tid; i < CIN * 81; i += 288) {
        float v = w[i];
        wsm[2 * i] = v; wsm[2 * i + 1] = v;
    }
    for (int i = tid; i < 2 * CIN * 26; i += 288) {
        int h = i / (CIN * 26), r = i % (CIN * 26);
        int ci = r / 26, rr = r % 26;
        float* rowp = pl + h * PLN + ci * CSTR + rr * RSTR;
        if (rr == 0 || rr == 25) {
            for (int c = 3; c <= 28; ++c) rowp[c] = 0.f;
        } else {
            rowp[3] = 0.f; rowp[28] = 0.f;
        }
    }

    u64 acc[2] = {0ull, 0ull};

    for (int j1 = 0; j1 < 3; ++j1) {
        int y1 = x1 + j1 - 1;
        if ((unsigned)y1 >= 24u) continue;
        for (int j2 = 0; j2 < 3; ++j2) {
            __syncthreads();
            for (int t = tid; t < 2 * CIN * 24; t += 288) {
                int h = t / (CIN * 24), r = t % (CIN * 24);
                int ci = r / 24, rr = 1 + r % 24;
                int y2 = bx * 2 + h + j2 - 1;
                float* dst = pl + h * PLN + ci * CSTR + rr * RSTR + 4;
                if ((unsigned)y2 < 24u) {
                    const float* src = in + ((((size_t)b * CIN + ci) * 24 + y1) * 24 + y2) * POOL_P
                                          + (rr - 1) * 24;
#pragma unroll
                    for (int c = 0; c < 6; ++c)
                        *(float4*)(dst + c * 4) = *(const float4*)(src + c * 4);
                } else {
                    float4 z = make_float4(0.f, 0.f, 0.f, 0.f);
#pragma unroll
                    for (int c = 0; c < 6; ++c) *(float4*)(dst + c * 4) = z;
                }
            }
            __syncthreads();

            const float* base = pl + half * PLN;
            for (int ci = 0; ci < CIN; ++ci) {
#pragma unroll
                for (int j3 = 0; j3 < 3; ++j3) {
                    const float* r0 = base + ci * CSTR + (x3 + j3) * RSTR + 3 + x4;
                    const float* r1 = r0 + RSTR;
                    u64 vd[4];
#pragma unroll
                    for (int t = 0; t < 4; ++t) vd[t] = pack2(r0[t], r1[t]);
                    const u64* wb = reinterpret_cast<const u64*>(
                        wsm + 2 * (ci * 81 + j1 * 27 + j2 * 9 + j3 * 3));
#pragma unroll
                    for (int j4 = 0; j4 < 3; ++j4) {
                        u64 wp = wb[j4];
                        fma2(acc[0], wp, vd[j4]);
                        fma2(acc[1], wp, vd[j4 + 1]);
                    }
                }
            }
        }
    }

    float b0 = bias[0];
    float2 c0 = unpack2(acc[0]);
    float2 c1 = unpack2(acc[1]);
    size_t base0 = (((size_t)b * 24 + x1) * 24 + x2) * POOL_P + x3 * 24 + x4;
    *(float2*)(out + base0)      = make_float2(fmaxf(c0.x + b0, 0.f), fmaxf(c1.x + b0, 0.f));
    *(float2*)(out + base0 + 24) = make_float2(fmaxf(c0.y + b0, 0.f), fmaxf(c1.y + b0, 0.f));
}

// host-side smem mirrors
static inline size_t conv_smem_bytes(int cin, int cout) {
    int cp2 = (cout + 1) & ~1;
    size_t wpad = ((size_t)cin * 81 * cp2 + 3) & ~(size_t)3;
    return (wpad + 2 * (size_t)cin * CSTR) * 4;
}
static inline size_t conv_cin1_smem_bytes(int cout) {
    int cp2 = (cout + 1) & ~1;
    size_t wpad = ((size_t)81 * cp2 + 3) & ~(size_t)3;
    return (wpad + 12 * (size_t)CSTR) * 4;
}
static inline size_t conv_c1_smem_bytes(int cin) {
    size_t wpad = (2 * (size_t)cin * 81 + 3) & ~(size_t)3;
    return (wpad + 2 * (size_t)cin * CSTR) * 4;
}

// ---------------------------------------------------------------------------
// Launch
// ---------------------------------------------------------------------------
extern "C" void kernel_launch(void* const* d_in, const int* in_sizes, int n_in,
                              void* d_out, int out_size) {
    const float* fA = (const float*)d_in[0];
    const float* fB = (const float*)d_in[1];
    const float* w1 = (const float*)d_in[2];
    const float* b1 = (const float*)d_in[3];
    const float* w2 = (const float*)d_in[4];
    const float* b2 = (const float*)d_in[5];
    const float* w3 = (const float*)d_in[6];
    const float* b3 = (const float*)d_in[7];
    float* out = (float*)d_out;

    float *gA, *gB, *invA, *invB, *cpool, *x1b, *x2b, *amax, *bmax;
    cudaGetSymbolAddress((void**)&gA, g_A);
    cudaGetSymbolAddress((void**)&gB, g_B);
    cudaGetSymbolAddress((void**)&invA, g_invnA);
    cudaGetSymbolAddress((void**)&invB, g_invnB);
    cudaGetSymbolAddress((void**)&cpool, g_cpool);
    cudaGetSymbolAddress((void**)&x1b, g_x1);
    cudaGetSymbolAddress((void**)&x2b, g_x2);
    cudaGetSymbolAddress((void**)&amax, g_amax);
    cudaGetSymbolAddress((void**)&bmax, g_bmax);

    size_t sm1 = conv_cin1_smem_bytes(10);   // ~48.2 KB
    size_t sm2 = conv_smem_bytes(10, 10);    // ~107.3 KB (2 CTAs/SM)
    size_t sm3 = conv_c1_smem_bytes(10);     // ~81.4 KB (2 CTAs/SM)
    size_t smg = 3 * 2 * STAGE_FLOATS * 4;   // 96 KB

    cudaFuncSetAttribute(gemm_pool_kernel, cudaFuncAttributeMaxDynamicSharedMemorySize, (int)smg);
    cudaFuncSetAttribute(conv4d_cin1_kernel<10>, cudaFuncAttributeMaxDynamicSharedMemorySize, (int)sm1);
    cudaFuncSetAttribute(conv4d_v4_kernel<10, 10>, cudaFuncAttributeMaxDynamicSharedMemorySize, (int)sm2);
    cudaFuncSetAttribute(conv4d_c1_kernel<10>, cudaFuncAttributeMaxDynamicSharedMemorySize, (int)sm3);

    // 1) inverse norms
    invnorm_kernel<<<(2 * BATCH * HW) / 256, 256>>>(fA, fB);

    // 2) transpose + normalize + tf32 round (A and B in ONE launch)
    transnorm_kernel<<<dim3(72, 32, 16), 256>>>(fA, fB, invA, invB, gA, gB);

    // 3) TF32 GEMM + pool + relu/L2 + fused row/col max reduction
    cudaMemsetAsync(amax, 0, BATCH * POOL_P * sizeof(float));
    cudaMemsetAsync(bmax, 0, BATCH * POOL_P * sizeof(float));
    gemm_pool_kernel<<<dim3(18, 18, BATCH), 128, smg>>>(gA, gB, cpool, amax, bmax);
    recip_kernel<<<(BATCH * POOL_P + 255) / 256, 256>>>(amax, bmax);

    // 4) neighbourhood consensus convs (conv1 applies mm #1 at load)
    dim3 cgrid(12, 24, BATCH);
    conv4d_cin1_kernel<10><<<cgrid, 288, sm1>>>(cpool, w1, b1, x1b, amax, bmax);
    conv4d_v4_kernel<10, 10><<<cgrid, 288, sm2>>>(x1b, w2, b2, x2b);
    conv4d_c1_kernel<10><<<cgrid, 288, sm3>>>(x2b, w3, b3, cpool);

    // 5) mutual matching #2 -> output
    cudaMemsetAsync(bmax, 0, BATCH * POOL_P * sizeof(float));
    maxfused_kernel<<<dim3(9, BATCH), 256>>>(cpool, amax, bmax);
    recip_kernel<<<(BATCH * POOL_P + 255) / 256, 256>>>(amax, bmax);
    mm_kernel<<<(POS_TOTAL / 4 + 255) / 256, 256>>>(cpool, amax, bmax, out);

    (void)in_sizes; (void)n_in; (void)out_size;
}

// round 16
// speedup vs baseline: 1.0297x; 1.0297x over previous
#include <cuda_runtime.h>
#include <cuda_bf16.h>

// ---------------------------------------------------------------------------
// Problem constants
// ---------------------------------------------------------------------------
#define BATCH 8
#define CHANNELS 1024
#define HW 2304           // 48*48
#define POOL_P 576        // 24*24
#define POS_TOTAL (BATCH*POOL_P*POOL_P)   // 2,654,208
#define EPS_L2 1e-6f
#define EPS_MM 1e-5f

typedef unsigned long long u64;

// ---------------------------------------------------------------------------
// Scratch (device globals; no allocation allowed)
// ---------------------------------------------------------------------------
__device__ float g_A[BATCH * HW * CHANNELS];
__device__ float g_B[BATCH * HW * CHANNELS];
__device__ float g_invnA[BATCH * HW];
__device__ float g_invnB[BATCH * HW];
__device__ float g_cpool[POS_TOTAL];
__device__ float g_x1[BATCH * 10 * POOL_P * POOL_P];
__device__ float g_x2[BATCH * 10 * POOL_P * POOL_P];
__device__ float g_amax[BATCH * POOL_P];      // max -> reciprocal (in place)
__device__ float g_bmax[BATCH * POOL_P];

// ---------------------------------------------------------------------------
// Helpers
// ---------------------------------------------------------------------------
__device__ __forceinline__ unsigned smem_u32(const void* p) {
    return (unsigned)__cvta_generic_to_shared(p);
}
__device__ __forceinline__ u64 pack2(float a, float b) {
    u64 r; asm("mov.b64 %0, {%1, %2};" : "=l"(r) : "f"(a), "f"(b)); return r;
}
__device__ __forceinline__ void fma2(u64& d, u64 a, u64 b) {
    asm("fma.rn.f32x2 %0, %1, %2, %0;" : "+l"(d) : "l"(a), "l"(b));
}
__device__ __forceinline__ float2 unpack2(u64 v) {
    float2 r; asm("mov.b64 {%0, %1}, %2;" : "=f"(r.x), "=f"(r.y) : "l"(v)); return r;
}
__device__ __forceinline__ float tf32r(float v) {
    unsigned t; asm("cvt.rna.tf32.f32 %0, %1;" : "=r"(t) : "f"(v));
    return __uint_as_float(t);
}

// ---------------------------------------------------------------------------
// 1) inverse L2 norm per (b, hw)
// ---------------------------------------------------------------------------
__global__ void invnorm_kernel(const float* __restrict__ A, const float* __restrict__ B) {
    int t = blockIdx.x * blockDim.x + threadIdx.x;
    if (t >= 2 * BATCH * HW) return;
    const float* f = (t < BATCH * HW) ? A : B;
    float* o = (t < BATCH * HW) ? g_invnA : g_invnB;
    int idx = t % (BATCH * HW);
    int b = idx / HW, hw = idx % HW;
    const float* p = f + (size_t)b * CHANNELS * HW + hw;
    float s = 0.f;
#pragma unroll 16
    for (int c = 0; c < CHANNELS; ++c) {
        float v = p[(size_t)c * HW];
        s = fmaf(v, v, s);
    }
    o[idx] = rsqrtf(s + EPS_L2);
}

// ---------------------------------------------------------------------------
// 2) transpose + normalize + tf32-round into MMA-fragment layout (one launch)
// ---------------------------------------------------------------------------
__global__ __launch_bounds__(256) void transnorm_kernel(
    const float* __restrict__ fA, const float* __restrict__ fB,
    const float* __restrict__ invA, const float* __restrict__ invB,
    float* __restrict__ outA, float* __restrict__ outB) {
    __shared__ float sm[32][33];
    int zz = blockIdx.z;
    int mode = zz >> 3;
    int b = zz & 7;
    const float* f = mode ? fB : fA;
    const float* invn = mode ? invB : invA;
    float* out = mode ? outB : outA;

    int pb = blockIdx.x;
    int c0 = blockIdx.y * 32;
    int g0 = pb * 8;
    int hbase = (g0 / 24) * 2;
    int wbase = (g0 % 24) * 2;
    int tid = threadIdx.x;

    for (int idx = tid; idx < 1024; idx += 256) {
        int ci = idx >> 5, pos = idx & 31;
        int hh = pos >> 4, ww = pos & 15;
        int hw = (hbase + hh) * 48 + wbase + ww;
        float v = f[((size_t)b * CHANNELS + c0 + ci) * HW + hw] * invn[b * HW + hw];
        int p_in = ((ww >> 1) << 2) | (hh << 1) | (ww & 1);
        sm[p_in][ci] = tf32r(v);
    }
    __syncthreads();

    int p0 = pb * 32;
    if (mode == 0) {
        int mt = tid >> 7, kt = (tid >> 5) & 3, lane = tid & 31;
        int rowin = lane >> 2, colin = lane & 3;
        float4 v;
        v.x = sm[mt * 16 + rowin][kt * 8 + colin];
        v.y = sm[mt * 16 + rowin + 8][kt * 8 + colin];
        v.z = sm[mt * 16 + rowin][kt * 8 + colin + 4];
        v.w = sm[mt * 16 + rowin + 8][kt * 8 + colin + 4];
        int rowblk = p0 >> 7;
        int mtile_g = ((p0 >> 4) & 7) + mt;
        int ktile_g = (c0 >> 3) + kt;
        size_t off = ((((size_t)b * 18 + rowblk) * 128 + ktile_g) * 8 + mtile_g) * 128
                     + lane * 4;
        *(float4*)(out + off) = v;
    } else {
        int colblk = p0 >> 7;
#pragma unroll
        for (int i = 0; i < 2; ++i) {
            int id = tid + i * 256;
            int nt = id >> 7, kt = (id >> 5) & 3, lane = id & 31;
            int rowin = lane >> 2, colin = lane & 3;
            float2 v;
            v.x = sm[nt * 8 + rowin][kt * 8 + colin];
            v.y = sm[nt * 8 + rowin][kt * 8 + colin + 4];
            int ntile_g = ((p0 >> 3) & 15) + nt;
            int ktile_g = (c0 >> 3) + kt;
            size_t off = ((((size_t)b * 18 + colblk) * 128 + ktile_g) * 16 + ntile_g) * 64
                         + lane * 2;
            *(float2*)(out + off) = v;
        }
    }
}

// ---------------------------------------------------------------------------
// 3) batched TF32 GEMM + fused 4x4 max-pool + relu/L2  (R13 form, no atomics)
// ---------------------------------------------------------------------------
#define STAGE_FLOATS 4096   // 4 ktiles * 1024 floats

__global__ __launch_bounds__(128) void gemm_pool_kernel(
    const float* __restrict__ A, const float* __restrict__ B,
    float* __restrict__ out) {
    extern __shared__ char smem_raw[];
    float* As = (float*)smem_raw;            // [3][4096]
    float* Bs = As + 3 * STAGE_FLOATS;       // [3][4096]
    float* Cs = (float*)smem_raw;            // reused: [128][132]

    int b = blockIdx.z;
    const float* Ag = A + (size_t)b * HW * CHANNELS + (size_t)blockIdx.y * 128 * 1024;
    const float* Bg = B + (size_t)b * HW * CHANNELS + (size_t)blockIdx.x * 128 * 1024;

    int tid = threadIdx.x, lane = tid & 31, wid = tid >> 5;
    int wm = wid >> 1, wn = wid & 1;   // 2x2 warp grid, warp tile 64x64

    float acc[4][8][4];
#pragma unroll
    for (int i = 0; i < 4; ++i)
#pragma unroll
        for (int j = 0; j < 8; ++j)
#pragma unroll
            for (int k = 0; k < 4; ++k) acc[i][j][k] = 0.f;

    auto load_stage = [&](int s, int kt) {
        const float* ga = Ag + (size_t)kt * STAGE_FLOATS;
        const float* gb = Bg + (size_t)kt * STAGE_FLOATS;
#pragma unroll
        for (int i = 0; i < 8; ++i) {
            int idx = tid + i * 128;
            unsigned sa = smem_u32(As + s * STAGE_FLOATS + idx * 4);
            asm volatile("cp.async.cg.shared.global [%0], [%1], 16;\n" :: "r"(sa), "l"(ga + idx * 4));
            unsigned sb = smem_u32(Bs + s * STAGE_FLOATS + idx * 4);
            asm volatile("cp.async.cg.shared.global [%0], [%1], 16;\n" :: "r"(sb), "l"(gb + idx * 4));
        }
        asm volatile("cp.async.commit_group;\n");
    };

    const int KT = CHANNELS / 32;
    load_stage(0, 0);
    load_stage(1, 1);
    for (int kt = 0; kt < KT; ++kt) {
        if (kt + 2 < KT) {
            asm volatile("cp.async.wait_group 1;\n");
        } else {
            asm volatile("cp.async.wait_group 0;\n");
        }
        __syncthreads();
        if (kt + 2 < KT) load_stage((kt + 2) % 3, kt + 2);
        int cur = kt % 3;
        const float* Ab = As + cur * STAGE_FLOATS;
        const float* Bb = Bs + cur * STAGE_FLOATS;
#pragma unroll
        for (int kk = 0; kk < 4; ++kk) {
            uint2 bf[8];
#pragma unroll
            for (int ni = 0; ni < 8; ++ni)
                bf[ni] = *(const uint2*)(Bb + ((kk * 16 + wn * 8 + ni) * 32 + lane) * 2);
#pragma unroll
            for (int mi = 0; mi < 4; ++mi) {
                uint4 af = *(const uint4*)(Ab + ((kk * 8 + wm * 4 + mi) * 32 + lane) * 4);
#pragma unroll
                for (int ni = 0; ni < 8; ++ni) {
                    asm volatile(
                        "mma.sync.aligned.m16n8k8.row.col.f32.tf32.tf32.f32 "
                        "{%0,%1,%2,%3}, {%4,%5,%6,%7}, {%8,%9}, {%0,%1,%2,%3};\n"
                        : "+f"(acc[mi][ni][0]), "+f"(acc[mi][ni][1]),
                          "+f"(acc[mi][ni][2]), "+f"(acc[mi][ni][3])
                        : "r"(af.x), "r"(af.y), "r"(af.z), "r"(af.w),
                          "r"(bf[ni].x), "r"(bf[ni].y));
                }
            }
        }
    }
    __syncthreads();

#pragma unroll
    for (int mi = 0; mi < 4; ++mi) {
#pragma unroll
        for (int ni = 0; ni < 8; ++ni) {
            int r0 = wm * 64 + mi * 16 + (lane >> 2);
            int c0 = wn * 64 + ni * 8 + (lane & 3) * 2;
            Cs[r0 * 132 + c0]           = acc[mi][ni][0];
            Cs[r0 * 132 + c0 + 1]       = acc[mi][ni][1];
            Cs[(r0 + 8) * 132 + c0]     = acc[mi][ni][2];
            Cs[(r0 + 8) * 132 + c0 + 1] = acc[mi][ni][3];
        }
    }
    __syncthreads();

#pragma unroll
    for (int o = 0; o < 8; ++o) {
        int idx = tid * 8 + o;
        int pp = idx >> 5, qq = idx & 31;
        float m = -1e30f;
#pragma unroll
        for (int i = 0; i < 4; ++i)
#pragma unroll
            for (int j = 0; j < 4; ++j)
                m = fmaxf(m, Cs[(pp * 4 + i) * 132 + qq * 4 + j]);
        m = fmaxf(m, 0.f);
        float v = m * rsqrtf(m * m + EPS_L2);
        out[((size_t)b * POOL_P + blockIdx.y * 32 + pp) * POOL_P + blockIdx.x * 32 + qq] = v;
    }
}

// ---------------------------------------------------------------------------
// 4) fused single-pass row+col maxes (bmax must be pre-zeroed)
// ---------------------------------------------------------------------------
__global__ __launch_bounds__(256) void maxfused_kernel(
    const float* __restrict__ X, float* __restrict__ amax, float* __restrict__ bmax) {
    __shared__ int colm_s[POOL_P];
    int b = blockIdx.y;
    int r0 = blockIdx.x * 64;
    int tid = threadIdx.x, lane = tid & 31, wid = tid >> 5;

    for (int i = tid; i < POOL_P; i += 256) colm_s[i] = 0;
    __syncthreads();

    float colm[18];
#pragma unroll
    for (int i = 0; i < 18; ++i) colm[i] = 0.f;

    const float* base = X + (size_t)b * POOL_P * POOL_P;
#pragma unroll
    for (int rr = 0; rr < 8; ++rr) {
        int row = r0 + wid * 8 + rr;
        const float* p = base + (size_t)row * POOL_P;
        float rm = 0.f;
#pragma unroll
        for (int i = 0; i < 18; ++i) {
            float v = p[lane + i * 32];
            rm = fmaxf(rm, v);
            colm[i] = fmaxf(colm[i], v);
        }
#pragma unroll
        for (int s = 16; s; s >>= 1) rm = fmaxf(rm, __shfl_down_sync(0xffffffffu, rm, s));
        if (lane == 0) amax[b * POOL_P + row] = rm;
    }
#pragma unroll
    for (int i = 0; i < 18; ++i)
        atomicMax(&colm_s[lane + i * 32], __float_as_int(colm[i]));
    __syncthreads();
    for (int i = tid; i < POOL_P; i += 256)
        atomicMax((int*)&bmax[b * POOL_P + i], colm_s[i]);
}

// convert max -> 1/(max+eps)
__global__ void recip_kernel(float* __restrict__ amax, float* __restrict__ bmax) {
    int i = blockIdx.x * blockDim.x + threadIdx.x;
    if (i < BATCH * POOL_P) {
        amax[i] = 1.0f / (amax[i] + EPS_MM);
        bmax[i] = 1.0f / (bmax[i] + EPS_MM);
    }
}

// ---------------------------------------------------------------------------
// 5) mutual matching, float4 (final pass only)
// ---------------------------------------------------------------------------
__global__ __launch_bounds__(256) void mm_kernel(
    const float* __restrict__ X, const float* __restrict__ am,
    const float* __restrict__ bm, float* __restrict__ O) {
    int i4 = blockIdx.x * blockDim.x + threadIdx.x;
    if (i4 >= POS_TOTAL / 4) return;
    int i = i4 * 4;
    int q = i % POOL_P;
    int pr = (i / POOL_P) % POOL_P;
    int b = i / (POOL_P * POOL_P);
    float a = am[b * POOL_P + pr];
    const float* bp = bm + b * POOL_P + q;
    float4 c = *(const float4*)(X + i);
    float4 o;
    o.x = c.x * (c.x * a) * (c.x * bp[0]);
    o.y = c.y * (c.y * a) * (c.y * bp[1]);
    o.z = c.z * (c.z * a) * (c.z * bp[2]);
    o.w = c.w * (c.w * a) * (c.w * bp[3]);
    *(float4*)(O + i) = o;
}

// ---------------------------------------------------------------------------
// 6) Conv4d FFMA2 v4 (conv2): 2x2 tile/thread, CTA-uniform j1 skip.
// ---------------------------------------------------------------------------
#define RSTR 36              // plane row stride (floats)
#define CSTR (26 * RSTR)     // 936 floats per channel

template <int CIN, int COUT>
__global__ __launch_bounds__(288) void conv4d_v4_kernel(
    const float* __restrict__ in, const float* __restrict__ w,
    const float* __restrict__ bias, float* __restrict__ out) {
    constexpr int CP2 = (COUT + 1) & ~1;
    constexpr int COP = CP2 / 2;
    constexpr int WPAD = (CIN * 81 * CP2 + 3) & ~3;
    constexpr int PLN = CIN * CSTR;
    extern __shared__ float sm[];
    float* wsm = sm;
    float* pl = sm + WPAD;

    int tid = threadIdx.x;
    int b = blockIdx.z, x1 = blockIdx.y, bx = blockIdx.x;
    int half = tid / 144, u = tid % 144;
    int x3 = 2 * (u / 12), x4 = 2 * (u % 12);
    int x2 = bx * 2 + half;

    for (int i = tid; i < CIN * 81 * CP2; i += 288) {
        int co = i % CP2;
        int rest = i / CP2;
        int ci = rest / 81, tap = rest % 81;
        wsm[i] = (co < COUT) ? w[(co * CIN + ci) * 81 + tap] : 0.f;
    }
    for (int i = tid; i < 2 * CIN * 26; i += 288) {
        int h = i / (CIN * 26), r = i % (CIN * 26);
        int ci = r / 26, rr = r % 26;
        float* rowp = pl + h * PLN + ci * CSTR + rr * RSTR;
        if (rr == 0 || rr == 25) {
            for (int c = 3; c <= 28; ++c) rowp[c] = 0.f;
        } else {
            rowp[3] = 0.f; rowp[28] = 0.f;
        }
    }

    u64 acc[COP][4];
#pragma unroll
    for (int cp = 0; cp < COP; ++cp)
#pragma unroll
        for (int o = 0; o < 4; ++o) acc[cp][o] = 0ull;

    for (int j1 = 0; j1 < 3; ++j1) {
        int y1 = x1 + j1 - 1;
        if ((unsigned)y1 >= 24u) continue;
        for (int j2 = 0; j2 < 3; ++j2) {
            __syncthreads();
            for (int t = tid; t < 2 * CIN * 24; t += 288) {
                int h = t / (CIN * 24), r = t % (CIN * 24);
                int ci = r / 24, rr = 1 + r % 24;
                int y2 = bx * 2 + h + j2 - 1;
                float* dst = pl + h * PLN + ci * CSTR + rr * RSTR + 4;
                if ((unsigned)y2 < 24u) {
                    const float* src = in + ((((size_t)b * CIN + ci) * 24 + y1) * 24 + y2) * POOL_P
                                          + (rr - 1) * 24;
#pragma unroll
                    for (int c = 0; c < 6; ++c)
                        *(float4*)(dst + c * 4) = *(const float4*)(src + c * 4);
                } else {
                    float4 z = make_float4(0.f, 0.f, 0.f, 0.f);
#pragma unroll
                    for (int c = 0; c < 6; ++c) *(float4*)(dst + c * 4) = z;
                }
            }
            __syncthreads();

            const float* base = pl + half * PLN;
            for (int ci = 0; ci < CIN; ++ci) {
#pragma unroll
                for (int j3 = 0; j3 < 3; ++j3) {
                    const float* r0 = base + ci * CSTR + (x3 + j3) * RSTR + 3 + x4;
                    const float* r1 = r0 + RSTR;
                    u64 vd0[4], vd1[4];
#pragma unroll
                    for (int t = 0; t < 4; ++t) {
                        float a = r0[t]; vd0[t] = pack2(a, a);
                        float c2 = r1[t]; vd1[t] = pack2(c2, c2);
                    }
                    const float* wb = wsm + (ci * 81 + j1 * 27 + j2 * 9 + j3 * 3) * CP2;
#pragma unroll
                    for (int j4 = 0; j4 < 3; ++j4) {
#pragma unroll
                        for (int cp = 0; cp < COP; ++cp) {
                            u64 wp = *reinterpret_cast<const u64*>(wb + j4 * CP2 + cp * 2);
                            fma2(acc[cp][0], wp, vd0[j4]);
                            fma2(acc[cp][1], wp, vd0[j4 + 1]);
                            fma2(acc[cp][2], wp, vd1[j4]);
                            fma2(acc[cp][3], wp, vd1[j4 + 1]);
                        }
                    }
                }
            }
        }
    }

    int pos0 = x3 * 24 + x4;
#pragma unroll
    for (int cp = 0; cp < COP; ++cp) {
        int co0 = 2 * cp, co1 = co0 + 1;
        float2 q0 = unpack2(acc[cp][0]);
        float2 q1 = unpack2(acc[cp][1]);
        float2 q2 = unpack2(acc[cp][2]);
        float2 q3 = unpack2(acc[cp][3]);
        float b0 = bias[co0];
        size_t base0 = ((((size_t)b * COUT + co0) * 24 + x1) * 24 + x2) * POOL_P + pos0;
        *(float2*)(out + base0)      = make_float2(fmaxf(q0.x + b0, 0.f), fmaxf(q1.x + b0, 0.f));
        *(float2*)(out + base0 + 24) = make_float2(fmaxf(q2.x + b0, 0.f), fmaxf(q3.x + b0, 0.f));
        if (co1 < COUT) {
            float b1 = bias[co1];
            size_t base1 = ((((size_t)b * COUT + co1) * 24 + x1) * 24 + x2) * POOL_P + pos0;
            *(float2*)(out + base1)      = make_float2(fmaxf(q0.y + b1, 0.f), fmaxf(q1.y + b1, 0.f));
            *(float2*)(out + base1 + 24) = make_float2(fmaxf(q2.y + b1, 0.f), fmaxf(q3.y + b1, 0.f));
        }
    }
}

// ---------------------------------------------------------------------------
// 6a) Conv1 (CIN=1): preload ALL 12 distinct haloed planes once, with
//     mutual-matching #1 applied at load (each element loaded exactly once).
// ---------------------------------------------------------------------------
template <int COUT>
__global__ __launch_bounds__(288) void conv4d_cin1_kernel(
    const float* __restrict__ in, const float* __restrict__ w,
    const float* __restrict__ bias, float* __restrict__ out,
    const float* __restrict__ ainv, const float* __restrict__ binv) {
    constexpr int CP2 = (COUT + 1) & ~1;
    constexpr int COP = CP2 / 2;
    constexpr int WPAD = (81 * CP2 + 3) & ~3;
    extern __shared__ float sm[];
    float* wsm = sm;                    // [81][CP2]
    float* pl = sm + WPAD;              // [12][CSTR]

    int tid = threadIdx.x;
    int b = blockIdx.z, x1 = blockIdx.y, bx = blockIdx.x;
    int half = tid / 144, u = tid % 144;
    int x3 = 2 * (u / 12), x4 = 2 * (u % 12);
    int x2 = bx * 2 + half;

    for (int i = tid; i < 81 * CP2; i += 288) {
        int co = i % CP2, tap = i / CP2;
        wsm[i] = (co < COUT) ? w[co * 81 + tap] : 0.f;
    }
    for (int i = tid; i < 12 * 26; i += 288) {
        int p = i / 26, rr = i % 26;
        float* rowp = pl + p * CSTR + rr * RSTR;
        if (rr == 0 || rr == 25) {
            for (int c = 3; c <= 28; ++c) rowp[c] = 0.f;
        } else {
            rowp[3] = 0.f; rowp[28] = 0.f;
        }
    }
    {
        int p = tid / 24, rr = 1 + tid % 24;
        int y1 = x1 + (p >> 2) - 1;
        int y2 = bx * 2 + (p & 3) - 1;
        float* dst = pl + p * CSTR + rr * RSTR + 4;
        if ((unsigned)y1 < 24u && (unsigned)y2 < 24u) {
            const float* src = in + (((size_t)b * 24 + y1) * 24 + y2) * POOL_P + (rr - 1) * 24;
            float a = ainv[b * POOL_P + y1 * 24 + y2];
            const float* bp = binv + b * POOL_P + (rr - 1) * 24;
#pragma unroll
            for (int c = 0; c < 6; ++c) {
                float4 vv = *(const float4*)(src + c * 4);
                const float* bq = bp + c * 4;
                vv.x = vv.x * (vv.x * a) * (vv.x * bq[0]);
                vv.y = vv.y * (vv.y * a) * (vv.y * bq[1]);
                vv.z = vv.z * (vv.z * a) * (vv.z * bq[2]);
                vv.w = vv.w * (vv.w * a) * (vv.w * bq[3]);
                *(float4*)(dst + c * 4) = vv;
            }
        } else {
            float4 z = make_float4(0.f, 0.f, 0.f, 0.f);
#pragma unroll
            for (int c = 0; c < 6; ++c) *(float4*)(dst + c * 4) = z;
        }
    }
    __syncthreads();

    u64 acc[COP][4];
#pragma unroll
    for (int cp = 0; cp < COP; ++cp)
#pragma unroll
        for (int o = 0; o < 4; ++o) acc[cp][o] = 0ull;

#pragma unroll
    for (int g = 0; g < 9; ++g) {
        int j1 = g / 3, j2 = g % 3;
        if ((unsigned)(x1 + j1 - 1) >= 24u) continue;
        const float* base = pl + (j1 * 4 + j2 + half) * CSTR;
#pragma unroll
        for (int j3 = 0; j3 < 3; ++j3) {
            const float* r0 = base + (x3 + j3) * RSTR + 3 + x4;
            const float* r1 = r0 + RSTR;
            u64 vd0[4], vd1[4];
#pragma unroll
            for (int t = 0; t < 4; ++t) {
                float a = r0[t]; vd0[t] = pack2(a, a);
                float c2 = r1[t]; vd1[t] = pack2(c2, c2);
            }
            const float* wb = wsm + (j1 * 27 + j2 * 9 + j3 * 3) * CP2;
#pragma unroll
            for (int j4 = 0; j4 < 3; ++j4) {
#pragma unroll
                for (int cp = 0; cp < COP; ++cp) {
                    u64 wp = *reinterpret_cast<const u64*>(wb + j4 * CP2 + cp * 2);
                    fma2(acc[cp][0], wp, vd0[j4]);
                    fma2(acc[cp][1], wp, vd0[j4 + 1]);
                    fma2(acc[cp][2], wp, vd1[j4]);
                    fma2(acc[cp][3], wp, vd1[j4 + 1]);
                }
            }
        }
    }

    int pos0 = x3 * 24 + x4;
#pragma unroll
    for (int cp = 0; cp < COP; ++cp) {
        int co0 = 2 * cp, co1 = co0 + 1;
        float2 q0 = unpack2(acc[cp][0]);
        float2 q1 = unpack2(acc[cp][1]);
        float2 q2 = unpack2(acc[cp][2]);
        float2 q3 = unpack2(acc[cp][3]);
        float b0 = bias[co0];
        size_t base0 = ((((size_t)b * COUT + co0) * 24 + x1) * 24 + x2) * POOL_P + pos0;
        *(float2*)(out + base0)      = make_float2(fmaxf(q0.x + b0, 0.f), fmaxf(q1.x + b0, 0.f));
        *(float2*)(out + base0 + 24) = make_float2(fmaxf(q2.x + b0, 0.f), fmaxf(q3.x + b0, 0.f));
        if (co1 < COUT) {
            float b1 = bias[co1];
            size_t base1 = ((((size_t)b * COUT + co1) * 24 + x1) * 24 + x2) * POOL_P + pos0;
            *(float2*)(out + base1)      = make_float2(fmaxf(q0.y + b1, 0.f), fmaxf(q1.y + b1, 0.f));
            *(float2*)(out + base1 + 24) = make_float2(fmaxf(q2.y + b1, 0.f), fmaxf(q3.y + b1, 0.f));
        }
    }
}

// ---------------------------------------------------------------------------
// 6b) Conv3 (COUT=1): row-pair f32x2; CTA-uniform j1 skip.
// ---------------------------------------------------------------------------
template <int CIN>
__global__ __launch_bounds__(288) void conv4d_c1_kernel(
    const float* __restrict__ in, const float* __restrict__ w,
    const float* __restrict__ bias, float* __restrict__ out) {
    constexpr int WPAD = (2 * CIN * 81 + 3) & ~3;
    constexpr int PLN = CIN * CSTR;
    extern __shared__ float sm[];
    float* wsm = sm;
    float* pl = sm + WPAD;

    int tid = threadIdx.x;
    int b = blockIdx.z, x1 = blockIdx.y, bx = blockIdx.x;
    int half = tid / 144, u = tid % 144;
    int x3 = 2 * (u / 12), x4 = 2 * (u % 12);
    int x2 = bx * 2 + half;

    for (int i = tid; i < CIN * 81; i += 288) {
        float v = w[i];
        wsm[2 * i] = v; wsm[2 * i + 1] = v;
    }
    for (int i = tid; i < 2 * CIN * 26; i += 288) {
        int h = i / (CIN * 26), r = i % (CIN * 26);
        int ci = r / 26, rr = r % 26;
        float* rowp = pl + h * PLN + ci * CSTR + rr * RSTR;
        if (rr == 0 || rr == 25) {
            for (int c = 3; c <= 28; ++c) rowp[c] = 0.f;
        } else {
            rowp[3] = 0.f; rowp[28] = 0.f;
        }
    }

    u64 acc[2] = {0ull, 0ull};

    for (int j1 = 0; j1 < 3; ++j1) {
        int y1 = x1 + j1 - 1;
        if ((unsigned)y1 >= 24u) continue;
        for (int j2 = 0; j2 < 3; ++j2) {
            __syncthreads();
            for (int t = tid; t < 2 * CIN * 24; t += 288) {
                int h = t / (CIN * 24), r = t % (CIN * 24);
                int ci = r / 24, rr = 1 + r % 24;
                int y2 = bx * 2 + h + j2 - 1;
                float* dst = pl + h * PLN + ci * CSTR + rr * RSTR + 4;
                if ((unsigned)y2 < 24u) {
                    const float* src = in + ((((size_t)b * CIN + ci) * 24 + y1) * 24 + y2) * POOL_P
                                          + (rr - 1) * 24;
#pragma unroll
                    for (int c = 0; c < 6; ++c)
                        *(float4*)(dst + c * 4) = *(const float4*)(src + c * 4);
                } else {
                    float4 z = make_float4(0.f, 0.f, 0.f, 0.f);
#pragma unroll
                    for (int c = 0; c < 6; ++c) *(float4*)(dst + c * 4) = z;
                }
            }
            __syncthreads();

            const float* base = pl + half * PLN;
            for (int ci = 0; ci < CIN; ++ci) {
#pragma unroll
                for (int j3 = 0; j3 < 3; ++j3) {
                    const float* r0 = base + ci * CSTR + (x3 + j3) * RSTR + 3 + x4;
                    const float* r1 = r0 + RSTR;
                    u64 vd[4];
#pragma unroll
                    for (int t = 0; t < 4; ++t) vd[t] = pack2(r0[t], r1[t]);
                    const u64* wb = reinterpret_cast<const u64*>(
                        wsm + 2 * (ci * 81 + j1 * 27 + j2 * 9 + j3 * 3));
#pragma unroll
                    for (int j4 = 0; j4 < 3; ++j4) {
                        u64 wp = wb[j4];
                        fma2(acc[0], wp, vd[j4]);
                        fma2(acc[1], wp, vd[j4 + 1]);
                    }
                }
            }
        }
    }

    float b0 = bias[0];
    float2 c0 = unpack2(acc[0]);
    float2 c1 = unpack2(acc[1]);
    size_t base0 = (((size_t)b * 24 + x1) * 24 + x2) * POOL_P + x3 * 24 + x4;
    *(float2*)(out + base0)      = make_float2(fmaxf(c0.x + b0, 0.f), fmaxf(c1.x + b0, 0.f));
    *(float2*)(out + base0 + 24) = make_float2(fmaxf(c0.y + b0, 0.f), fmaxf(c1.y + b0, 0.f));
}

// host-side smem mirrors
static inline size_t conv_smem_bytes(int cin, int cout) {
    int cp2 = (cout + 1) & ~1;
    size_t wpad = ((size_t)cin * 81 * cp2 + 3) & ~(size_t)3;
    return (wpad + 2 * (size_t)cin * CSTR) * 4;
}
static inline size_t conv_cin1_smem_bytes(int cout) {
    int cp2 = (cout + 1) & ~1;
    size_t wpad = ((size_t)81 * cp2 + 3) & ~(size_t)3;
    return (wpad + 12 * (size_t)CSTR) * 4;
}
static inline size_t conv_c1_smem_bytes(int cin) {
    size_t wpad = (2 * (size_t)cin * 81 + 3) & ~(size_t)3;
    return (wpad + 2 * (size_t)cin * CSTR) * 4;
}

// ---------------------------------------------------------------------------
// Launch
// ---------------------------------------------------------------------------
extern "C" void kernel_launch(void* const* d_in, const int* in_sizes, int n_in,
                              void* d_out, int out_size) {
    const float* fA = (const float*)d_in[0];
    const float* fB = (const float*)d_in[1];
    const float* w1 = (const float*)d_in[2];
    const float* b1 = (const float*)d_in[3];
    const float* w2 = (const float*)d_in[4];
    const float* b2 = (const float*)d_in[5];
    const float* w3 = (const float*)d_in[6];
    const float* b3 = (const float*)d_in[7];
    float* out = (float*)d_out;

    float *gA, *gB, *invA, *invB, *cpool, *x1b, *x2b, *amax, *bmax;
    cudaGetSymbolAddress((void**)&gA, g_A);
    cudaGetSymbolAddress((void**)&gB, g_B);
    cudaGetSymbolAddress((void**)&invA, g_invnA);
    cudaGetSymbolAddress((void**)&invB, g_invnB);
    cudaGetSymbolAddress((void**)&cpool, g_cpool);
    cudaGetSymbolAddress((void**)&x1b, g_x1);
    cudaGetSymbolAddress((void**)&x2b, g_x2);
    cudaGetSymbolAddress((void**)&amax, g_amax);
    cudaGetSymbolAddress((void**)&bmax, g_bmax);

    size_t sm1 = conv_cin1_smem_bytes(10);   // ~48.2 KB
    size_t sm2 = conv_smem_bytes(10, 10);    // ~107.3 KB (2 CTAs/SM)
    size_t sm3 = conv_c1_smem_bytes(10);     // ~81.4 KB (2 CTAs/SM)
    size_t smg = 3 * 2 * STAGE_FLOATS * 4;   // 96 KB

    cudaFuncSetAttribute(gemm_pool_kernel, cudaFuncAttributeMaxDynamicSharedMemorySize, (int)smg);
    cudaFuncSetAttribute(conv4d_cin1_kernel<10>, cudaFuncAttributeMaxDynamicSharedMemorySize, (int)sm1);
    cudaFuncSetAttribute(conv4d_v4_kernel<10, 10>, cudaFuncAttributeMaxDynamicSharedMemorySize, (int)sm2);
    cudaFuncSetAttribute(conv4d_c1_kernel<10>, cudaFuncAttributeMaxDynamicSharedMemorySize, (int)sm3);

    // 1) inverse norms
    invnorm_kernel<<<(2 * BATCH * HW) / 256, 256>>>(fA, fB);

    // 2) transpose + normalize + tf32 round (A and B in ONE launch)
    transnorm_kernel<<<dim3(72, 32, 16), 256>>>(fA, fB, invA, invB, gA, gB);

    // 3) TF32 GEMM + pool + relu/L2
    gemm_pool_kernel<<<dim3(18, 18, BATCH), 128, smg>>>(gA, gB, cpool);

    // 4) maxes of pooled corr (reciprocals); mm #1 fused into conv1's load
    cudaMemsetAsync(bmax, 0, BATCH * POOL_P * sizeof(float));
    maxfused_kernel<<<dim3(9, BATCH), 256>>>(cpool, amax, bmax);
    recip_kernel<<<(BATCH * POOL_P + 255) / 256, 256>>>(amax, bmax);

    // 5) neighbourhood consensus convs (conv1 applies mm #1 at load)
    dim3 cgrid(12, 24, BATCH);
    conv4d_cin1_kernel<10><<<cgrid, 288, sm1>>>(cpool, w1, b1, x1b, amax, bmax);
    conv4d_v4_kernel<10, 10><<<cgrid, 288, sm2>>>(x1b, w2, b2, x2b);
    conv4d_c1_kernel<10><<<cgrid, 288, sm3>>>(x2b, w3, b3, cpool);

    // 6) mutual matching #2 -> output
    cudaMemsetAsync(bmax, 0, BATCH * POOL_P * sizeof(float));
    maxfused_kernel<<<dim3(9, BATCH), 256>>>(cpool, amax, bmax);
    recip_kernel<<<(BATCH * POOL_P + 255) / 256, 256>>>(amax, bmax);
    mm_kernel<<<(POS_TOTAL / 4 + 255) / 256, 256>>>(cpool, amax, bmax, out);

    (void)in_sizes; (void)n_in; (void)out_size;
}